// round 2
// baseline (speedup 1.0000x reference)
#include <cuda_runtime.h>
#include <math.h>

#define BATCH 8
#define HF    128
#define PIX   (HF*HF)
#define NOG   384
#define NIMP  96
#define NPTS  128
#define INC   512
#define HID2  256
#define KFEAT 514
#define COUT  2

// ---------------- scratch (no allocations allowed) ----------------
__device__ float g_points[BATCH*NPTS*2];
__device__ float g_feat  [BATCH*NPTS*KFEAT];
__device__ float g_h1    [BATCH*NPTS*INC];
__device__ float g_h2    [BATCH*NPTS*HID2];

// ---------------- bilinear helper (exact replica of _point_sample math) ----
struct Bilin { int l00,l10,l01,l11; float w00,w10,w01,w11; };

__device__ __forceinline__ Bilin make_bilin(float px, float py) {
    Bilin r;
    float g0 = 2.0f*px - 1.0f;
    float g1 = 2.0f*py - 1.0f;
    float gx = ((g0 + 1.0f)*(float)HF - 1.0f)*0.5f;
    float gy = ((g1 + 1.0f)*(float)HF - 1.0f)*0.5f;
    float x0f = floorf(gx), y0f = floorf(gy);
    float wx1 = gx - x0f,  wy1 = gy - y0f;
    float wx0 = 1.0f - wx1, wy0 = 1.0f - wy1;
    int x0 = (int)x0f, y0 = (int)y0f;
    int x1 = x0 + 1,   y1 = y0 + 1;
    bool vx0 = (x0 >= 0) && (x0 <= HF-1);
    bool vx1 = (x1 >= 0) && (x1 <= HF-1);
    bool vy0 = (y0 >= 0) && (y0 <= HF-1);
    bool vy1 = (y1 >= 0) && (y1 <= HF-1);
    int x0c = min(max(x0,0),HF-1), x1c = min(max(x1,0),HF-1);
    int y0c = min(max(y0,0),HF-1), y1c = min(max(y1,0),HF-1);
    r.l00 = y0c*HF + x0c;  r.l10 = y0c*HF + x1c;
    r.l01 = y1c*HF + x0c;  r.l11 = y1c*HF + x1c;
    r.w00 = (vx0 && vy0) ? wx0*wy0 : 0.0f;
    r.w10 = (vx1 && vy0) ? wx1*wy0 : 0.0f;
    r.w01 = (vx0 && vy1) ? wx0*wy1 : 0.0f;
    r.w11 = (vx1 && vy1) ? wx1*wy1 : 0.0f;
    return r;
}

// ---------------- K1: sampling points (unc top-96 + zeros + rand) ---------
__global__ void __launch_bounds__(NOG) k_points(
    const float* __restrict__ out, const float* __restrict__ over_gen,
    const float* __restrict__ rand_point, float* __restrict__ pts_out)
{
    int b = blockIdx.x, tid = threadIdx.x;
    __shared__ float s_unc[NOG];
    const float* ob = out + (size_t)b*2*PIX;
    float px = 0.f, py = 0.f;

    {
        px = over_gen[((size_t)b*NOG + tid)*2 + 0];
        py = over_gen[((size_t)b*NOG + tid)*2 + 1];
        Bilin bl = make_bilin(px, py);
        float a00 = ob[bl.l00], b00 = ob[PIX + bl.l00];
        float a10 = ob[bl.l10], b10 = ob[PIX + bl.l10];
        float a01 = ob[bl.l01], b01 = ob[PIX + bl.l01];
        float a11 = ob[bl.l11], b11 = ob[PIX + bl.l11];
        // sorted channels (desc) of a 2-channel map == per-pixel max/min
        float og0 = bl.w00*fmaxf(a00,b00) + bl.w10*fmaxf(a10,b10)
                  + bl.w01*fmaxf(a01,b01) + bl.w11*fmaxf(a11,b11);
        float og1 = bl.w00*fminf(a00,b00) + bl.w10*fminf(a10,b10)
                  + bl.w01*fminf(a01,b01) + bl.w11*fminf(a11,b11);
        s_unc[tid] = og1 - og0;   // == -(og0 - og1)
    }
    __syncthreads();

    {
        float u = s_unc[tid];
        int rank = 0;
        #pragma unroll 8
        for (int j = 0; j < NOG; j++) {
            float uj = s_unc[j];
            rank += (uj > u) || (uj == u && j < tid);  // stable (lowest idx first)
        }
        if (rank < NIMP) {
            float2 p = make_float2(px, py);
            ((float2*)g_points)[b*NPTS + rank] = p;
            ((float2*)pts_out )[b*NPTS + rank] = p;
        }
    }
    if (tid < 16) {
        // coverage points: provably (0,0) (trunc of values < 1)
        float2 z = make_float2(0.f, 0.f);
        ((float2*)g_points)[b*NPTS + NIMP + tid] = z;
        ((float2*)pts_out )[b*NPTS + NIMP + tid] = z;
        // rand points
        float2 rp = ((const float2*)rand_point)[b*16 + tid];
        ((float2*)g_points)[b*NPTS + NIMP + 16 + tid] = rp;
        ((float2*)pts_out )[b*NPTS + NIMP + 16 + tid] = rp;
    }
}

// ---------------- K2: gather feat rows = [coarse(2) | fine(512)] ----------
__global__ void __launch_bounds__(128) k_feat(
    const float* __restrict__ out, const float* __restrict__ res2)
{
    int idx = blockIdx.x;            // b*128 + n
    int b = idx >> 7;
    int tid = threadIdx.x;
    float2 p = ((const float2*)g_points)[idx];
    Bilin bl = make_bilin(p.x, p.y);
    const float* rb = res2 + (size_t)b*INC*PIX;
    float* frow = g_feat + (size_t)idx*KFEAT;

    #pragma unroll 4
    for (int c = tid; c < INC; c += 128) {
        const float* pp = rb + (size_t)c*PIX;
        frow[2 + c] = bl.w00*pp[bl.l00] + bl.w10*pp[bl.l10]
                    + bl.w01*pp[bl.l01] + bl.w11*pp[bl.l11];
    }
    if (tid < 2) {
        const float* pp = out + (size_t)(b*2 + tid)*PIX;
        frow[tid] = bl.w00*pp[bl.l00] + bl.w10*pp[bl.l10]
                  + bl.w01*pp[bl.l01] + bl.w11*pp[bl.l11];
    }
}

// ---------------- K3/K4: fused GEMM + LayerNorm + exact GELU --------------
// STAGE 1: g_feat[1024,514] @ w1[514,512]  -> g_h1
// STAGE 2: g_h1 [1024,512] @ w2[512,256]  -> g_h2
template<int STAGE>
__global__ void __launch_bounds__(128) k_mlp(
    const float* __restrict__ W, const float* __restrict__ bias,
    const float* __restrict__ gamma, const float* __restrict__ beta)
{
    constexpr int K   = (STAGE == 1) ? KFEAT : INC;
    constexpr int N   = (STAGE == 1) ? INC   : HID2;
    constexpr int CPT = N / 128;
    const float* X = (STAGE == 1) ? g_feat : g_h1;
    float*       Y = (STAGE == 1) ? g_h1   : g_h2;

    __shared__ float sX[8][K];
    __shared__ float sO[8][N];
    int tid  = threadIdx.x;
    int row0 = blockIdx.x * 8;

    #pragma unroll
    for (int r = 0; r < 8; r++)
        for (int i = tid; i < K; i += 128)
            sX[r][i] = X[(size_t)(row0 + r)*K + i];
    __syncthreads();

    float acc[8][CPT];
    #pragma unroll
    for (int r = 0; r < 8; r++)
        #pragma unroll
        for (int c = 0; c < CPT; c++) acc[r][c] = 0.0f;

    #pragma unroll 4
    for (int k = 0; k < K; k++) {
        float w[CPT];
        #pragma unroll
        for (int c = 0; c < CPT; c++) w[c] = W[(size_t)k*N + tid + c*128];
        #pragma unroll
        for (int r = 0; r < 8; r++) {
            float xv = sX[r][k];
            #pragma unroll
            for (int c = 0; c < CPT; c++) acc[r][c] = fmaf(xv, w[c], acc[r][c]);
        }
    }

    #pragma unroll
    for (int r = 0; r < 8; r++)
        #pragma unroll
        for (int c = 0; c < CPT; c++)
            sO[r][tid + c*128] = acc[r][c] + bias[tid + c*128];
    __syncthreads();

    // LayerNorm + GELU(exact erf): each warp handles 2 rows
    int warp = tid >> 5, lane = tid & 31;
    for (int r = warp; r < 8; r += 4) {
        float s = 0.0f;
        for (int i = lane; i < N; i += 32) s += sO[r][i];
        #pragma unroll
        for (int o = 16; o; o >>= 1) s += __shfl_xor_sync(0xffffffff, s, o);
        float m = s / (float)N;
        float v = 0.0f;
        for (int i = lane; i < N; i += 32) { float d = sO[r][i] - m; v += d*d; }
        #pragma unroll
        for (int o = 16; o; o >>= 1) v += __shfl_xor_sync(0xffffffff, v, o);
        float inv = rsqrtf(v / (float)N + 1e-5f);
        for (int i = lane; i < N; i += 32) {
            float yv = (sO[r][i] - m) * inv * gamma[i] + beta[i];
            yv = 0.5f * yv * (1.0f + erff(yv * 0.70710678118654752440f));
            Y[(size_t)(row0 + r)*N + i] = yv;
        }
    }
}

// ---------------- K5: final projection + dropout-mask + coarse ------------
__global__ void __launch_bounds__(256) k_final(
    const float* __restrict__ w3, const float* __restrict__ b3,
    const float* __restrict__ mask, float* __restrict__ rend)
{
    int b = blockIdx.x, tid = threadIdx.x;
    int n = tid >> 1, c = tid & 1;
    const float* h = g_h2 + (size_t)(b*NPTS + n)*HID2;
    float acc = 0.0f;
    #pragma unroll 8
    for (int k = 0; k < HID2; k++) acc = fmaf(h[k], w3[k*COUT + c], acc);
    float pred   = acc + b3[c];
    float coarse = g_feat[(size_t)(b*NPTS + n)*KFEAT + c];
    float m      = mask[(size_t)(b*COUT + c)*NPTS + n];
    rend[(size_t)(b*COUT + c)*NPTS + n] = pred * m + coarse;
}

// ---------------- launch ----------------
extern "C" void kernel_launch(void* const* d_in, const int* in_sizes, int n_in,
                              void* d_out, int out_size)
{
    // metadata order matches reference signature; d_in[0] = x (unused, shape-only)
    const float* res2       = (const float*)d_in[1];
    const float* out        = (const float*)d_in[2];
    const float* over_gen   = (const float*)d_in[3];
    const float* rand_point = (const float*)d_in[4];
    const float* mask       = (const float*)d_in[5];
    const float* w1  = (const float*)d_in[6];
    const float* b1  = (const float*)d_in[7];
    const float* g1  = (const float*)d_in[8];
    const float* be1 = (const float*)d_in[9];
    const float* w2  = (const float*)d_in[10];
    const float* b2  = (const float*)d_in[11];
    const float* g2  = (const float*)d_in[12];
    const float* be2 = (const float*)d_in[13];
    const float* w3  = (const float*)d_in[14];
    const float* b3  = (const float*)d_in[15];

    float* o_rend = (float*)d_out;                      // [8,2,128]
    float* o_pts  = o_rend + (size_t)BATCH*COUT*NPTS;   // [8,128,2]

    k_points<<<BATCH, NOG>>>(out, over_gen, rand_point, o_pts);
    k_feat  <<<BATCH*NPTS, 128>>>(out, res2);
    k_mlp<1><<<BATCH*NPTS/8, 128>>>(w1, b1, g1, be1);
    k_mlp<2><<<BATCH*NPTS/8, 128>>>(w2, b2, g2, be2);
    k_final <<<BATCH, 256>>>(w3, b3, mask, o_rend);
}

// round 3
// speedup vs baseline: 2.0182x; 2.0182x over previous
#include <cuda_runtime.h>
#include <math.h>

#define BATCH 8
#define HF    128
#define PIX   (HF*HF)
#define NOG   384
#define NIMP  96
#define NPTS  128
#define INC   512
#define HID2  256
#define KFEAT 514
#define KFP   528          // padded feat K (zeros in [514,528))
#define COUT  2
#define NROWS (BATCH*NPTS) // 1024

// ---------------- scratch ----------------
__device__ float g_points[BATCH*NPTS*2];
__device__ float g_feat  [NROWS*KFP];     // padded
__device__ float g_t1    [NROWS*INC];     // gemm1 raw
__device__ float g_h1    [NROWS*INC];     // post LN+GELU
__device__ float g_t2    [NROWS*HID2];    // gemm2 raw
__device__ float g_h2    [NROWS*HID2];    // post LN+GELU

// ---------------- bilinear helper ----------------
struct Bilin { int l00,l10,l01,l11; float w00,w10,w01,w11; };

__device__ __forceinline__ Bilin make_bilin(float px, float py) {
    Bilin r;
    float gx = ((2.0f*px - 1.0f + 1.0f)*(float)HF - 1.0f)*0.5f;
    float gy = ((2.0f*py - 1.0f + 1.0f)*(float)HF - 1.0f)*0.5f;
    float x0f = floorf(gx), y0f = floorf(gy);
    float wx1 = gx - x0f,  wy1 = gy - y0f;
    float wx0 = 1.0f - wx1, wy0 = 1.0f - wy1;
    int x0 = (int)x0f, y0 = (int)y0f;
    int x1 = x0 + 1,   y1 = y0 + 1;
    bool vx0 = (x0 >= 0) && (x0 <= HF-1);
    bool vx1 = (x1 >= 0) && (x1 <= HF-1);
    bool vy0 = (y0 >= 0) && (y0 <= HF-1);
    bool vy1 = (y1 >= 0) && (y1 <= HF-1);
    int x0c = min(max(x0,0),HF-1), x1c = min(max(x1,0),HF-1);
    int y0c = min(max(y0,0),HF-1), y1c = min(max(y1,0),HF-1);
    r.l00 = y0c*HF + x0c;  r.l10 = y0c*HF + x1c;
    r.l01 = y1c*HF + x0c;  r.l11 = y1c*HF + x1c;
    r.w00 = (vx0 && vy0) ? wx0*wy0 : 0.0f;
    r.w10 = (vx1 && vy0) ? wx1*wy0 : 0.0f;
    r.w01 = (vx0 && vy1) ? wx0*wy1 : 0.0f;
    r.w11 = (vx1 && vy1) ? wx1*wy1 : 0.0f;
    return r;
}

// ---------------- K1: sampling points ----------------
__global__ void __launch_bounds__(NOG) k_points(
    const float* __restrict__ out, const float* __restrict__ over_gen,
    const float* __restrict__ rand_point, float* __restrict__ pts_out)
{
    int b = blockIdx.x, tid = threadIdx.x;
    __shared__ float s_unc[NOG];
    const float* ob = out + (size_t)b*2*PIX;

    float px = over_gen[((size_t)b*NOG + tid)*2 + 0];
    float py = over_gen[((size_t)b*NOG + tid)*2 + 1];
    {
        Bilin bl = make_bilin(px, py);
        float a00 = ob[bl.l00], b00 = ob[PIX + bl.l00];
        float a10 = ob[bl.l10], b10 = ob[PIX + bl.l10];
        float a01 = ob[bl.l01], b01 = ob[PIX + bl.l01];
        float a11 = ob[bl.l11], b11 = ob[PIX + bl.l11];
        float og0 = bl.w00*fmaxf(a00,b00) + bl.w10*fmaxf(a10,b10)
                  + bl.w01*fmaxf(a01,b01) + bl.w11*fmaxf(a11,b11);
        float og1 = bl.w00*fminf(a00,b00) + bl.w10*fminf(a10,b10)
                  + bl.w01*fminf(a01,b01) + bl.w11*fminf(a11,b11);
        s_unc[tid] = og1 - og0;
    }
    __syncthreads();
    {
        float u = s_unc[tid];
        int rank = 0;
        #pragma unroll 8
        for (int j = 0; j < NOG; j++) {
            float uj = s_unc[j];
            rank += (uj > u) || (uj == u && j < tid);   // stable
        }
        if (rank < NIMP) {
            float2 p = make_float2(px, py);
            ((float2*)g_points)[b*NPTS + rank] = p;
            ((float2*)pts_out )[b*NPTS + rank] = p;
        }
    }
    if (tid < 16) {
        float2 z = make_float2(0.f, 0.f);
        ((float2*)g_points)[b*NPTS + NIMP + tid] = z;
        ((float2*)pts_out )[b*NPTS + NIMP + tid] = z;
        float2 rp = ((const float2*)rand_point)[b*16 + tid];
        ((float2*)g_points)[b*NPTS + NIMP + 16 + tid] = rp;
        ((float2*)pts_out )[b*NPTS + NIMP + 16 + tid] = rp;
    }
}

// ---------------- K2: gather feat rows = [coarse(2) | fine(512) | pad(14)] --
__global__ void __launch_bounds__(128) k_feat(
    const float* __restrict__ out, const float* __restrict__ res2)
{
    int idx = blockIdx.x;            // b*128 + n
    int b = idx >> 7;
    int tid = threadIdx.x;
    float2 p = ((const float2*)g_points)[idx];
    Bilin bl = make_bilin(p.x, p.y);
    const float* rb = res2 + (size_t)b*INC*PIX;
    float* frow = g_feat + (size_t)idx*KFP;

    #pragma unroll 4
    for (int c = tid; c < INC; c += 128) {
        const float* pp = rb + (size_t)c*PIX;
        frow[2 + c] = bl.w00*pp[bl.l00] + bl.w10*pp[bl.l10]
                    + bl.w01*pp[bl.l01] + bl.w11*pp[bl.l11];
    }
    if (tid < 2) {
        const float* pp = out + (size_t)(b*2 + tid)*PIX;
        frow[tid] = bl.w00*pp[bl.l00] + bl.w10*pp[bl.l10]
                  + bl.w01*pp[bl.l01] + bl.w11*pp[bl.l11];
    }
    if (tid >= 2 && tid < 16) frow[512 + tid] = 0.0f;   // pad [514,528)
}

// ---------------- register-tiled SGEMM, double-buffered --------------------
// C[M,N] = A[M,KP(zeros beyond KREAL)] @ W[KREAL,N]
// block tile BM x 64, BK=16, 256 threads, micro-tile TM x 4
template<int KREAL, int KP, int LDA, int N, int BM, int TM>
__global__ void __launch_bounds__(256) k_gemm(
    const float* __restrict__ A, const float* __restrict__ W,
    float* __restrict__ C)
{
    constexpr int BK = 16, BN = 64, TN = 4;
    constexpr int KT = KP / BK;
    __shared__ float sA[2][BK][BM + 4];
    __shared__ float sW[2][BK][BN];

    int tid = threadIdx.x;
    int tx = tid & 15, ty = tid >> 4;
    int row0 = blockIdx.y * BM, col0 = blockIdx.x * BN;

    int a_m = tid >> 2, a_k = (tid & 3) * 4;    // A loader: float4 along k
    int w_k = tid >> 4, w_n = (tid & 15) * 4;   // W loader: float4 along n
    const bool aload = (BM * 4 == 256) || (tid < BM * 4);

    float4 av = make_float4(0,0,0,0), wv;
    if (aload) av = *(const float4*)&A[(size_t)(row0 + a_m)*LDA + a_k];
    wv = (w_k < KREAL) ? *(const float4*)&W[(size_t)w_k*N + col0 + w_n]
                       : make_float4(0,0,0,0);
    if (aload) {
        sA[0][a_k+0][a_m] = av.x; sA[0][a_k+1][a_m] = av.y;
        sA[0][a_k+2][a_m] = av.z; sA[0][a_k+3][a_m] = av.w;
    }
    *(float4*)&sW[0][w_k][w_n] = wv;
    __syncthreads();

    float acc[TM][TN];
    #pragma unroll
    for (int i = 0; i < TM; i++)
        #pragma unroll
        for (int j = 0; j < TN; j++) acc[i][j] = 0.0f;

    for (int t = 0; t < KT; t++) {
        int buf = t & 1;
        if (t + 1 < KT) {
            int k0 = (t + 1) * BK;
            if (aload) av = *(const float4*)&A[(size_t)(row0 + a_m)*LDA + k0 + a_k];
            int kg = k0 + w_k;
            wv = (kg < KREAL) ? *(const float4*)&W[(size_t)kg*N + col0 + w_n]
                              : make_float4(0,0,0,0);
        }
        #pragma unroll
        for (int kk = 0; kk < BK; kk++) {
            float a[TM], w[TN];
            if (TM == 4) {
                float4 v = *(float4*)&sA[buf][kk][ty*4];
                a[0]=v.x; a[1]=v.y; a[2]=v.z; a[3]=v.w;
            } else {
                float2 v = *(float2*)&sA[buf][kk][ty*2];
                a[0]=v.x; a[1]=v.y;
            }
            float4 wv4 = *(float4*)&sW[buf][kk][tx*4];
            w[0]=wv4.x; w[1]=wv4.y; w[2]=wv4.z; w[3]=wv4.w;
            #pragma unroll
            for (int i = 0; i < TM; i++)
                #pragma unroll
                for (int j = 0; j < TN; j++)
                    acc[i][j] = fmaf(a[i], w[j], acc[i][j]);
        }
        if (t + 1 < KT) {
            int nb = buf ^ 1;
            if (aload) {
                sA[nb][a_k+0][a_m] = av.x; sA[nb][a_k+1][a_m] = av.y;
                sA[nb][a_k+2][a_m] = av.z; sA[nb][a_k+3][a_m] = av.w;
            }
            *(float4*)&sW[nb][w_k][w_n] = wv;
            __syncthreads();
        }
    }

    #pragma unroll
    for (int i = 0; i < TM; i++) {
        float4 v = make_float4(acc[i][0], acc[i][1], acc[i][2], acc[i][3]);
        *(float4*)&C[(size_t)(row0 + ty*TM + i)*N + col0 + tx*4] = v;
    }
}

// ---------------- LN + exact GELU (warp per row) ---------------------------
template<int N>
__global__ void __launch_bounds__(256) k_lngelu(
    const float* __restrict__ Xr, const float* __restrict__ bias,
    const float* __restrict__ gamma, const float* __restrict__ beta,
    float* __restrict__ Y)
{
    constexpr int V = N / 128;   // float4s per lane
    int warp = threadIdx.x >> 5, lane = threadIdx.x & 31;
    int row = blockIdx.x * 8 + warp;
    const float4* x = (const float4*)(Xr + (size_t)row*N);
    const float4* b4 = (const float4*)bias;
    const float4* g4 = (const float4*)gamma;
    const float4* e4 = (const float4*)beta;
    float4* y = (float4*)(Y + (size_t)row*N);

    float4 v[V];
    float s = 0.0f;
    #pragma unroll
    for (int i = 0; i < V; i++) {
        int c = i*32 + lane;
        float4 t = x[c], bb = b4[c];
        t.x += bb.x; t.y += bb.y; t.z += bb.z; t.w += bb.w;
        v[i] = t;
        s += t.x + t.y + t.z + t.w;
    }
    #pragma unroll
    for (int o = 16; o; o >>= 1) s += __shfl_xor_sync(0xffffffff, s, o);
    float m = s / (float)N;
    float var = 0.0f;
    #pragma unroll
    for (int i = 0; i < V; i++) {
        float dx = v[i].x - m, dy = v[i].y - m, dz = v[i].z - m, dw = v[i].w - m;
        var += dx*dx + dy*dy + dz*dz + dw*dw;
    }
    #pragma unroll
    for (int o = 16; o; o >>= 1) var += __shfl_xor_sync(0xffffffff, var, o);
    float inv = rsqrtf(var / (float)N + 1e-5f);

    #pragma unroll
    for (int i = 0; i < V; i++) {
        int c = i*32 + lane;
        float4 gg = g4[c], ee = e4[c], t = v[i];
        float4 o4;
        float z;
        z = (t.x - m)*inv*gg.x + ee.x; o4.x = 0.5f*z*(1.0f + erff(z*0.70710678118654752440f));
        z = (t.y - m)*inv*gg.y + ee.y; o4.y = 0.5f*z*(1.0f + erff(z*0.70710678118654752440f));
        z = (t.z - m)*inv*gg.z + ee.z; o4.z = 0.5f*z*(1.0f + erff(z*0.70710678118654752440f));
        z = (t.w - m)*inv*gg.w + ee.w; o4.w = 0.5f*z*(1.0f + erff(z*0.70710678118654752440f));
        y[c] = o4;
    }
}

// ---------------- K_final: warp-per-point projection + mask + coarse -------
__global__ void __launch_bounds__(256) k_final(
    const float* __restrict__ w3, const float* __restrict__ b3,
    const float* __restrict__ mask, float* __restrict__ rend)
{
    int warp = threadIdx.x >> 5, lane = threadIdx.x & 31;
    int idx = blockIdx.x * 8 + warp;    // b*128 + n
    int b = idx >> 7, n = idx & 127;
    const float* h = g_h2 + (size_t)idx*HID2;
    float a0 = 0.0f, a1 = 0.0f;
    #pragma unroll
    for (int j = 0; j < HID2/32; j++) {
        int k = lane + j*32;
        float hv = h[k];
        float2 w = ((const float2*)w3)[k];
        a0 = fmaf(hv, w.x, a0);
        a1 = fmaf(hv, w.y, a1);
    }
    #pragma unroll
    for (int o = 16; o; o >>= 1) {
        a0 += __shfl_xor_sync(0xffffffff, a0, o);
        a1 += __shfl_xor_sync(0xffffffff, a1, o);
    }
    if (lane == 0) {
        float c0 = g_feat[(size_t)idx*KFP + 0];
        float c1 = g_feat[(size_t)idx*KFP + 1];
        float m0 = mask[(size_t)(b*COUT + 0)*NPTS + n];
        float m1 = mask[(size_t)(b*COUT + 1)*NPTS + n];
        rend[(size_t)(b*COUT + 0)*NPTS + n] = (a0 + b3[0])*m0 + c0;
        rend[(size_t)(b*COUT + 1)*NPTS + n] = (a1 + b3[1])*m1 + c1;
    }
}

// ---------------- launch ----------------
extern "C" void kernel_launch(void* const* d_in, const int* in_sizes, int n_in,
                              void* d_out, int out_size)
{
    const float* res2       = (const float*)d_in[1];
    const float* out        = (const float*)d_in[2];
    const float* over_gen   = (const float*)d_in[3];
    const float* rand_point = (const float*)d_in[4];
    const float* mask       = (const float*)d_in[5];
    const float* w1  = (const float*)d_in[6];
    const float* b1  = (const float*)d_in[7];
    const float* g1  = (const float*)d_in[8];
    const float* be1 = (const float*)d_in[9];
    const float* w2  = (const float*)d_in[10];
    const float* b2  = (const float*)d_in[11];
    const float* g2  = (const float*)d_in[12];
    const float* be2 = (const float*)d_in[13];
    const float* w3  = (const float*)d_in[14];
    const float* b3  = (const float*)d_in[15];

    float* o_rend = (float*)d_out;                      // [8,2,128]
    float* o_pts  = o_rend + (size_t)BATCH*COUT*NPTS;   // [8,128,2]

    float* gf;  cudaGetSymbolAddress((void**)&gf,  g_feat);
    float* gt1; cudaGetSymbolAddress((void**)&gt1, g_t1);
    float* gh1; cudaGetSymbolAddress((void**)&gh1, g_h1);
    float* gt2; cudaGetSymbolAddress((void**)&gt2, g_t2);
    float* gh2; cudaGetSymbolAddress((void**)&gh2, g_h2);

    k_points<<<BATCH, NOG>>>(out, over_gen, rand_point, o_pts);
    k_feat  <<<BATCH*NPTS, 128>>>(out, res2);

    // stage 1: [1024,528p] @ [514,512]
    dim3 g1g(INC/64, NROWS/64);
    k_gemm<KFEAT, KFP, KFP, INC, 64, 4><<<g1g, 256>>>(gf, w1, gt1);
    k_lngelu<INC><<<NROWS/8, 256>>>(gt1, b1, g1, be1, gh1);

    // stage 2: [1024,512] @ [512,256]
    dim3 g2g(HID2/64, NROWS/32);
    k_gemm<INC, INC, INC, HID2, 32, 2><<<g2g, 256>>>(gh1, w2, gt2);
    k_lngelu<HID2><<<NROWS/8, 256>>>(gt2, b2, g2, be2, gh2);

    k_final<<<NROWS/8, 256>>>(w3, b3, mask, o_rend);
}

// round 4
// speedup vs baseline: 2.0887x; 1.0350x over previous
#include <cuda_runtime.h>
#include <math.h>

#define BATCH 8
#define HF    128
#define PIX   (HF*HF)
#define NOG   384
#define NIMP  96
#define NPTS  128
#define INC   512
#define HID2  256
#define KFEAT 514
#define KFP   528
#define COUT  2
#define NROWS (BATCH*NPTS) // 1024

// ---------------- scratch ----------------
__device__ float g_points[BATCH*NPTS*2];
__device__ float g_feat  [NROWS*KFP];
__device__ float g_t1    [NROWS*INC];
__device__ float g_h1    [NROWS*INC];
__device__ float g_t2    [NROWS*HID2];

// ---------------- bilinear helper ----------------
struct Bilin { int l00,l10,l01,l11; float w00,w10,w01,w11; };

__device__ __forceinline__ Bilin make_bilin(float px, float py) {
    Bilin r;
    float gx = ((2.0f*px - 1.0f + 1.0f)*(float)HF - 1.0f)*0.5f;
    float gy = ((2.0f*py - 1.0f + 1.0f)*(float)HF - 1.0f)*0.5f;
    float x0f = floorf(gx), y0f = floorf(gy);
    float wx1 = gx - x0f,  wy1 = gy - y0f;
    float wx0 = 1.0f - wx1, wy0 = 1.0f - wy1;
    int x0 = (int)x0f, y0 = (int)y0f;
    int x1 = x0 + 1,   y1 = y0 + 1;
    bool vx0 = (x0 >= 0) && (x0 <= HF-1);
    bool vx1 = (x1 >= 0) && (x1 <= HF-1);
    bool vy0 = (y0 >= 0) && (y0 <= HF-1);
    bool vy1 = (y1 >= 0) && (y1 <= HF-1);
    int x0c = min(max(x0,0),HF-1), x1c = min(max(x1,0),HF-1);
    int y0c = min(max(y0,0),HF-1), y1c = min(max(y1,0),HF-1);
    r.l00 = y0c*HF + x0c;  r.l10 = y0c*HF + x1c;
    r.l01 = y1c*HF + x0c;  r.l11 = y1c*HF + x1c;
    r.w00 = (vx0 && vy0) ? wx0*wy0 : 0.0f;
    r.w10 = (vx1 && vy0) ? wx1*wy0 : 0.0f;
    r.w01 = (vx0 && vy1) ? wx0*wy1 : 0.0f;
    r.w11 = (vx1 && vy1) ? wx1*wy1 : 0.0f;
    return r;
}

// ---------------- K1: sampling points ----------------
__global__ void __launch_bounds__(NOG) k_points(
    const float* __restrict__ out, const float* __restrict__ over_gen,
    const float* __restrict__ rand_point, float* __restrict__ pts_out)
{
    int b = blockIdx.x, tid = threadIdx.x;
    __shared__ float s_unc[NOG];
    const float* ob = out + (size_t)b*2*PIX;

    float px = over_gen[((size_t)b*NOG + tid)*2 + 0];
    float py = over_gen[((size_t)b*NOG + tid)*2 + 1];
    {
        Bilin bl = make_bilin(px, py);
        float a00 = ob[bl.l00], b00 = ob[PIX + bl.l00];
        float a10 = ob[bl.l10], b10 = ob[PIX + bl.l10];
        float a01 = ob[bl.l01], b01 = ob[PIX + bl.l01];
        float a11 = ob[bl.l11], b11 = ob[PIX + bl.l11];
        float og0 = bl.w00*fmaxf(a00,b00) + bl.w10*fmaxf(a10,b10)
                  + bl.w01*fmaxf(a01,b01) + bl.w11*fmaxf(a11,b11);
        float og1 = bl.w00*fminf(a00,b00) + bl.w10*fminf(a10,b10)
                  + bl.w01*fminf(a01,b01) + bl.w11*fminf(a11,b11);
        s_unc[tid] = og1 - og0;
    }
    __syncthreads();
    {
        float u = s_unc[tid];
        int rank = 0;
        #pragma unroll 8
        for (int j = 0; j < NOG; j++) {
            float uj = s_unc[j];
            rank += (uj > u) || (uj == u && j < tid);   // stable
        }
        if (rank < NIMP) {
            float2 p = make_float2(px, py);
            ((float2*)g_points)[b*NPTS + rank] = p;
            ((float2*)pts_out )[b*NPTS + rank] = p;
        }
    }
    if (tid < 16) {
        float2 z = make_float2(0.f, 0.f);
        ((float2*)g_points)[b*NPTS + NIMP + tid] = z;
        ((float2*)pts_out )[b*NPTS + NIMP + tid] = z;
        float2 rp = ((const float2*)rand_point)[b*16 + tid];
        ((float2*)g_points)[b*NPTS + NIMP + 16 + tid] = rp;
        ((float2*)pts_out )[b*NPTS + NIMP + 16 + tid] = rp;
    }
}

// ---------------- K2: gather feat rows ----------------
__global__ void __launch_bounds__(128) k_feat(
    const float* __restrict__ out, const float* __restrict__ res2)
{
    int idx = blockIdx.x;            // b*128 + n
    int b = idx >> 7;
    int tid = threadIdx.x;
    float2 p = ((const float2*)g_points)[idx];
    Bilin bl = make_bilin(p.x, p.y);
    const float* rb = res2 + (size_t)b*INC*PIX;
    float* frow = g_feat + (size_t)idx*KFP;

    #pragma unroll 4
    for (int c = tid; c < INC; c += 128) {
        const float* pp = rb + (size_t)c*PIX;
        frow[2 + c] = bl.w00*pp[bl.l00] + bl.w10*pp[bl.l10]
                    + bl.w01*pp[bl.l01] + bl.w11*pp[bl.l11];
    }
    if (tid < 2) {
        const float* pp = out + (size_t)(b*2 + tid)*PIX;
        frow[tid] = bl.w00*pp[bl.l00] + bl.w10*pp[bl.l10]
                  + bl.w01*pp[bl.l01] + bl.w11*pp[bl.l11];
    }
    if (tid >= 2 && tid < 16) frow[512 + tid] = 0.0f;
}

// ---------------- register-tiled SGEMM + bias, double-buffered -------------
template<int KREAL, int KP, int LDA, int N, int BM, int TM>
__global__ void __launch_bounds__(256) k_gemm(
    const float* __restrict__ A, const float* __restrict__ W,
    const float* __restrict__ bias, float* __restrict__ C)
{
    constexpr int BK = 16, BN = 64, TN = 4;
    constexpr int KT = KP / BK;
    __shared__ float sA[2][BK][BM + 4];
    __shared__ float sW[2][BK][BN];

    int tid = threadIdx.x;
    int tx = tid & 15, ty = tid >> 4;
    int row0 = blockIdx.y * BM, col0 = blockIdx.x * BN;

    int a_m = tid >> 2, a_k = (tid & 3) * 4;
    int w_k = tid >> 4, w_n = (tid & 15) * 4;
    const bool aload = (BM * 4 == 256) || (tid < BM * 4);

    float4 av = make_float4(0,0,0,0), wv;
    if (aload) av = *(const float4*)&A[(size_t)(row0 + a_m)*LDA + a_k];
    wv = (w_k < KREAL) ? *(const float4*)&W[(size_t)w_k*N + col0 + w_n]
                       : make_float4(0,0,0,0);
    if (aload) {
        sA[0][a_k+0][a_m] = av.x; sA[0][a_k+1][a_m] = av.y;
        sA[0][a_k+2][a_m] = av.z; sA[0][a_k+3][a_m] = av.w;
    }
    *(float4*)&sW[0][w_k][w_n] = wv;
    __syncthreads();

    float acc[TM][TN];
    #pragma unroll
    for (int i = 0; i < TM; i++)
        #pragma unroll
        for (int j = 0; j < TN; j++) acc[i][j] = 0.0f;

    for (int t = 0; t < KT; t++) {
        int buf = t & 1;
        if (t + 1 < KT) {
            int k0 = (t + 1) * BK;
            if (aload) av = *(const float4*)&A[(size_t)(row0 + a_m)*LDA + k0 + a_k];
            int kg = k0 + w_k;
            wv = (kg < KREAL) ? *(const float4*)&W[(size_t)kg*N + col0 + w_n]
                              : make_float4(0,0,0,0);
        }
        #pragma unroll
        for (int kk = 0; kk < BK; kk++) {
            float a[TM], w[TN];
            if (TM == 4) {
                float4 v = *(float4*)&sA[buf][kk][ty*4];
                a[0]=v.x; a[1]=v.y; a[2]=v.z; a[3]=v.w;
            } else {
                float2 v = *(float2*)&sA[buf][kk][ty*2];
                a[0]=v.x; a[1]=v.y;
            }
            float4 wv4 = *(float4*)&sW[buf][kk][tx*4];
            w[0]=wv4.x; w[1]=wv4.y; w[2]=wv4.z; w[3]=wv4.w;
            #pragma unroll
            for (int i = 0; i < TM; i++)
                #pragma unroll
                for (int j = 0; j < TN; j++)
                    acc[i][j] = fmaf(a[i], w[j], acc[i][j]);
        }
        if (t + 1 < KT) {
            int nb = buf ^ 1;
            if (aload) {
                sA[nb][a_k+0][a_m] = av.x; sA[nb][a_k+1][a_m] = av.y;
                sA[nb][a_k+2][a_m] = av.z; sA[nb][a_k+3][a_m] = av.w;
            }
            *(float4*)&sW[nb][w_k][w_n] = wv;
            __syncthreads();
        }
    }

    float4 bv = *(const float4*)&bias[col0 + tx*4];
    #pragma unroll
    for (int i = 0; i < TM; i++) {
        float4 v = make_float4(acc[i][0] + bv.x, acc[i][1] + bv.y,
                               acc[i][2] + bv.z, acc[i][3] + bv.w);
        *(float4*)&C[(size_t)(row0 + ty*TM + i)*N + col0 + tx*4] = v;
    }
}

// ---------------- block reduce (128 threads / 4 warps) ---------------------
__device__ __forceinline__ float blk_reduce(float v, float* s, int tid) {
    int lane = tid & 31, warp = tid >> 5;
    #pragma unroll
    for (int o = 16; o; o >>= 1) v += __shfl_xor_sync(0xffffffff, v, o);
    if (lane == 0) s[warp] = v;
    __syncthreads();
    float r = s[0] + s[1] + s[2] + s[3];
    __syncthreads();
    return r;
}

// ---------------- K_ln1: LN + exact GELU (block per row) -------------------
__global__ void __launch_bounds__(128) k_ln1(
    const float* __restrict__ Xr, const float* __restrict__ gamma,
    const float* __restrict__ beta, float* __restrict__ Y)
{
    __shared__ float s[4];
    int row = blockIdx.x, tid = threadIdx.x;
    float4 t = ((const float4*)(Xr + (size_t)row*INC))[tid];
    float sum = blk_reduce(t.x + t.y + t.z + t.w, s, tid);
    float m = sum * (1.0f/INC);
    float dx = t.x-m, dy = t.y-m, dz = t.z-m, dw = t.w-m;
    float var = blk_reduce(dx*dx + dy*dy + dz*dz + dw*dw, s, tid);
    float inv = rsqrtf(var * (1.0f/INC) + 1e-5f);
    float4 gg = ((const float4*)gamma)[tid];
    float4 ee = ((const float4*)beta)[tid];
    float4 o4; float z;
    z = dx*inv*gg.x + ee.x; o4.x = 0.5f*z*(1.0f + erff(z*0.70710678118654752440f));
    z = dy*inv*gg.y + ee.y; o4.y = 0.5f*z*(1.0f + erff(z*0.70710678118654752440f));
    z = dz*inv*gg.z + ee.z; o4.z = 0.5f*z*(1.0f + erff(z*0.70710678118654752440f));
    z = dw*inv*gg.w + ee.w; o4.w = 0.5f*z*(1.0f + erff(z*0.70710678118654752440f));
    ((float4*)(Y + (size_t)row*INC))[tid] = o4;
}

// ---------------- K_ln2f: LN + GELU + w3 projection + mask + coarse --------
__global__ void __launch_bounds__(128) k_ln2f(
    const float* __restrict__ Xr, const float* __restrict__ gamma,
    const float* __restrict__ beta, const float* __restrict__ w3,
    const float* __restrict__ b3, const float* __restrict__ mask,
    float* __restrict__ rend)
{
    __shared__ float s[4];
    int row = blockIdx.x, tid = threadIdx.x;   // row = b*128 + n
    float2 t = ((const float2*)(Xr + (size_t)row*HID2))[tid];
    float sum = blk_reduce(t.x + t.y, s, tid);
    float m = sum * (1.0f/HID2);
    float dx = t.x-m, dy = t.y-m;
    float var = blk_reduce(dx*dx + dy*dy, s, tid);
    float inv = rsqrtf(var * (1.0f/HID2) + 1e-5f);
    float2 gg = ((const float2*)gamma)[tid];
    float2 ee = ((const float2*)beta)[tid];
    float z, hx, hy;
    z = dx*inv*gg.x + ee.x; hx = 0.5f*z*(1.0f + erff(z*0.70710678118654752440f));
    z = dy*inv*gg.y + ee.y; hy = 0.5f*z*(1.0f + erff(z*0.70710678118654752440f));
    // w3 rows 2*tid, 2*tid+1 -> float4 {w[k0][0], w[k0][1], w[k1][0], w[k1][1]}
    float4 ww = ((const float4*)w3)[tid];
    float a0 = blk_reduce(hx*ww.x + hy*ww.z, s, tid);
    float a1 = blk_reduce(hx*ww.y + hy*ww.w, s, tid);
    if (tid == 0) {
        int b = row >> 7, n = row & 127;
        float c0 = g_feat[(size_t)row*KFP + 0];
        float c1 = g_feat[(size_t)row*KFP + 1];
        float m0 = mask[(size_t)(b*COUT + 0)*NPTS + n];
        float m1 = mask[(size_t)(b*COUT + 1)*NPTS + n];
        rend[(size_t)(b*COUT + 0)*NPTS + n] = (a0 + b3[0])*m0 + c0;
        rend[(size_t)(b*COUT + 1)*NPTS + n] = (a1 + b3[1])*m1 + c1;
    }
}

// ---------------- launch ----------------
extern "C" void kernel_launch(void* const* d_in, const int* in_sizes, int n_in,
                              void* d_out, int out_size)
{
    const float* res2       = (const float*)d_in[1];
    const float* out        = (const float*)d_in[2];
    const float* over_gen   = (const float*)d_in[3];
    const float* rand_point = (const float*)d_in[4];
    const float* mask       = (const float*)d_in[5];
    const float* w1  = (const float*)d_in[6];
    const float* b1  = (const float*)d_in[7];
    const float* g1  = (const float*)d_in[8];
    const float* be1 = (const float*)d_in[9];
    const float* w2  = (const float*)d_in[10];
    const float* b2  = (const float*)d_in[11];
    const float* g2  = (const float*)d_in[12];
    const float* be2 = (const float*)d_in[13];
    const float* w3  = (const float*)d_in[14];
    const float* b3  = (const float*)d_in[15];

    float* o_rend = (float*)d_out;                      // [8,2,128]
    float* o_pts  = o_rend + (size_t)BATCH*COUT*NPTS;   // [8,128,2]

    float* gf;  cudaGetSymbolAddress((void**)&gf,  g_feat);
    float* gt1; cudaGetSymbolAddress((void**)&gt1, g_t1);
    float* gh1; cudaGetSymbolAddress((void**)&gh1, g_h1);
    float* gt2; cudaGetSymbolAddress((void**)&gt2, g_t2);

    k_points<<<BATCH, NOG>>>(out, over_gen, rand_point, o_pts);
    k_feat  <<<BATCH*NPTS, 128>>>(out, res2);

    dim3 g1g(INC/64, NROWS/64);
    k_gemm<KFEAT, KFP, KFP, INC, 64, 4><<<g1g, 256>>>(gf, w1, b1, gt1);
    k_ln1<<<NROWS, 128>>>(gt1, g1, be1, gh1);

    dim3 g2g(HID2/64, NROWS/32);
    k_gemm<INC, INC, INC, HID2, 32, 2><<<g2g, 256>>>(gh1, w2, b2, gt2);
    k_ln2f<<<NROWS, 128>>>(gt2, g2, be2, w3, b3, mask, o_rend);
}